// round 2
// baseline (speedup 1.0000x reference)
#include <cuda_runtime.h>
#include <math.h>

#define HOP      160
#define NFFT     512
#define WINLEN   320
#define NMELS    80
#define NBINS    257
#define PREEMPH  0.97f
#define LOG_EPSF 5.9604644775390625e-08f   /* 2^-24 */
#define STD_EPSF 1e-5f
#define BLANKF   27.0f

#define MAXB   32
#define MAXL   240000
#define MAXLP  (MAXL + NFFT)       /* 240512 */
#define MAXT   (MAXL / HOP + 1)    /* 1501 */

#define FB_PITCH 260               /* padded filterbank row pitch (16B aligned) */
#define SP_PITCH 261               /* odd pitch -> conflict-free scalar LDS    */
#define TT       32                /* frames per mel tile */

__device__ float g_ypad[MAXB * MAXLP];
__device__ float g_power[(size_t)MAXB * MAXT * NBINS];
__device__ __align__(16) float g_fbpad[NMELS * FB_PITCH];

/* xn may be int32 (JAX default, x64 off) or int64. Valid lengths are
 * >= 160000, so if word[1]==0 the layout is int64 (word[1] = high word of
 * element 0); otherwise it is int32. Only in-bounds words are read. */
__device__ __forceinline__ int load_seqlen(const int* __restrict__ xn32, int b) {
    int is64 = (xn32[1] == 0);
    int v = is64 ? xn32[2 * b] : xn32[b];
    return v / HOP + 1;
}

/* ------------------------------------------------------------------ K1:
 * preemphasis + reflect pad:  ypad[b][i] = y[reflect(i-256)]
 * y[j] = x[j] - 0.97*x[j-1]  (y[0] = x[0])
 */
__global__ void k_preemph(const float* __restrict__ x, int B, int L, int Lp) {
    int total = B * Lp;
    for (int gid = blockIdx.x * blockDim.x + threadIdx.x; gid < total;
         gid += gridDim.x * blockDim.x) {
        int b = gid / Lp;
        int i = gid - b * Lp;
        int j = i - NFFT / 2;
        int jj = (j < 0) ? -j : ((j >= L) ? (2 * L - 2 - j) : j);
        const float* xb = x + (size_t)b * L;
        float v = (jj == 0) ? xb[0] : (xb[jj] - PREEMPH * xb[jj - 1]);
        g_ypad[(size_t)b * Lp + i] = v;
    }
}

/* ------------------------------------------------------------------ K1b:
 * pad filterbank [80][257] -> [80][260] (tail zeros), float4-aligned rows
 */
__global__ void k_fbpad(const float* __restrict__ fb) {
    int i = blockIdx.x * blockDim.x + threadIdx.x;
    if (i < NMELS * FB_PITCH) {
        int m = i / FB_PITCH;
        int k = i - m * FB_PITCH;
        g_fbpad[i] = (k < NBINS) ? fb[m * NBINS + k] : 0.0f;
    }
}

/* ------------------------------------------------------------------ K2:
 * one block = 2 frames packed into one complex 512-pt DIF FFT.
 * 256 threads, each owns one butterfly per stage. Output: power spectra.
 */
__global__ void k_fft(int Lp, int T) {
    __shared__ float zr[NFFT], zi[NFFT];
    __shared__ float twr[NFFT / 2], twi[NFFT / 2];
    __shared__ float wwin[NFFT];

    const int tid = threadIdx.x;           /* 256 */
    const int tp  = blockIdx.x;
    const int b   = blockIdx.y;
    const int t0  = 2 * tp;
    const int t1  = 2 * tp + 1;
    const bool has1 = (t1 < T);

    /* twiddles: W_512^t = exp(-2*pi*i*t/512), t in [0,256) */
    {
        float s, c;
        sincosf((float)tid * (-6.283185307179586f / 512.0f), &s, &c);
        twr[tid] = c;
        twi[tid] = s;
    }
    /* hann window, support [96, 416) */
    for (int i = tid; i < NFFT; i += 256) {
        float w = 0.0f;
        if (i >= (NFFT - WINLEN) / 2 && i < (NFFT + WINLEN) / 2) {
            float ph = (float)(i - (NFFT - WINLEN) / 2) * (6.283185307179586f / (float)WINLEN);
            w = 0.5f - 0.5f * cosf(ph);
        }
        wwin[i] = w;
    }
    __syncthreads();

    const float* yb = g_ypad + (size_t)b * Lp;
    for (int i = tid; i < NFFT; i += 256) {
        float w = wwin[i];
        float a  = yb[t0 * HOP + i] * w;
        float bb = has1 ? (yb[t1 * HOP + i] * w) : 0.0f;
        zr[i] = a;
        zi[i] = bb;
    }
    __syncthreads();

    /* 9 DIF stages, natural in -> bit-reversed out */
    #pragma unroll
    for (int s = 0; s < 9; s++) {
        int h  = 256 >> s;
        int p  = tid & (h - 1);
        int i0 = ((tid >> (8 - s)) << (9 - s)) + p;
        int i1 = i0 + h;
        int tw = p << s;
        float ur = zr[i0], ui = zi[i0];
        float vr = zr[i1], vi = zi[i1];
        float dr = ur - vr, di = ui - vi;
        float cr = twr[tw], ci = twi[tw];
        zr[i0] = ur + vr;
        zi[i0] = ui + vi;
        zr[i1] = dr * cr - di * ci;
        zi[i1] = dr * ci + di * cr;
        __syncthreads();
    }

    /* unpack two real spectra + power.  thread tid does k=tid (and tid==0 does k=256) */
    for (int k = tid; k <= NFFT / 2; k += 256) {
        int kn = (NFFT - k) & (NFFT - 1);
        int r1 = __brev(k)  >> 23;
        int r2 = __brev(kn) >> 23;
        float z1r = zr[r1], z1i = zi[r1];
        float z2r = zr[r2], z2i = zi[r2];
        float Ar = 0.5f * (z1r + z2r);
        float Ai = 0.5f * (z1i - z2i);
        float Br = 0.5f * (z1i + z2i);
        float Bi = 0.5f * (z2r - z1r);
        size_t base = ((size_t)b * T + t0) * NBINS;
        g_power[base + k] = Ar * Ar + Ai * Ai;
        if (has1) g_power[base + NBINS + k] = Br * Br + Bi * Bi;
    }
}

/* ------------------------------------------------------------------ K3:
 * mel projection + log.  Block: 32-frame tile of one batch.
 * Power tile in shared (pitch 261), filterbank from global (L1-resident,
 * float4). Thread tile: 5 mels x 2 frames.
 */
__global__ void k_mel(float* __restrict__ out, int B, int T, int Tpad) {
    __shared__ float sp[TT * SP_PITCH];

    const int tid   = threadIdx.x;        /* 256 */
    const int b     = blockIdx.y;
    const int tbase = blockIdx.x * TT;

    for (int i = tid; i < TT * SP_PITCH; i += 256) {
        int tt = i / SP_PITCH;
        int k  = i - tt * SP_PITCH;
        int t  = tbase + tt;
        float v = 0.0f;
        if (t < T && k < NBINS) v = g_power[((size_t)b * T + t) * NBINS + k];
        sp[i] = v;
    }
    __syncthreads();

    const int mi = tid >> 4;              /* 0..15 -> mel group of 5   */
    const int ti = tid & 15;              /* 0..15 -> frame pair index */

    const float* p0p = sp + (2 * ti) * SP_PITCH;
    const float* p1p = p0p + SP_PITCH;

    float acc0[5] = {0.f, 0.f, 0.f, 0.f, 0.f};
    float acc1[5] = {0.f, 0.f, 0.f, 0.f, 0.f};

    for (int kq = 0; kq < FB_PITCH / 4; kq++) {   /* 65 quads covers 260 */
        int k0 = kq * 4;
        float a0 = p0p[k0], a1 = p0p[k0 + 1], a2 = p0p[k0 + 2], a3 = p0p[k0 + 3];
        float b0 = p1p[k0], b1 = p1p[k0 + 1], b2 = p1p[k0 + 2], b3 = p1p[k0 + 3];
        #pragma unroll
        for (int r = 0; r < 5; r++) {
            float4 f = __ldg((const float4*)(g_fbpad + (mi * 5 + r) * FB_PITCH + k0));
            acc0[r] += f.x * a0 + f.y * a1 + f.z * a2 + f.w * a3;
            acc1[r] += f.x * b0 + f.y * b1 + f.z * b2 + f.w * b3;
        }
    }

    #pragma unroll
    for (int r = 0; r < 5; r++) {
        int m = mi * 5 + r;
        int ta = tbase + 2 * ti;
        if (ta < T)     out[((size_t)b * NMELS + m) * Tpad + ta]     = logf(acc0[r] + LOG_EPSF);
        if (ta + 1 < T) out[((size_t)b * NMELS + m) * Tpad + ta + 1] = logf(acc1[r] + LOG_EPSF);
    }
}

/* ------------------------------------------------------------------ K4:
 * per-(b,m) masked mean/var normalization, in-place in d_out, BLANK pad.
 */
__global__ void k_norm(float* __restrict__ out, const int* __restrict__ xn32,
                       int T, int Tpad) {
    __shared__ float sx[1504];
    __shared__ float red[256];

    const int tid = threadIdx.x;          /* 256 */
    const int m   = blockIdx.x;
    const int b   = blockIdx.y;

    int n = load_seqlen(xn32, b);
    if (n < 2) n = 2;
    if (n > T) n = T;

    float* row = out + ((size_t)b * NMELS + m) * Tpad;

    float lsum = 0.0f;
    for (int t = tid; t < T; t += 256) {
        float v = row[t];
        sx[t] = v;
        if (t < n) lsum += v;
    }
    red[tid] = lsum;
    __syncthreads();
    for (int s = 128; s > 0; s >>= 1) {
        if (tid < s) red[tid] += red[tid + s];
        __syncthreads();
    }
    const float mean = red[0] / (float)n;
    __syncthreads();

    float lss = 0.0f;
    for (int t = tid; t < n; t += 256) {
        float d = sx[t] - mean;
        lss += d * d;
    }
    red[tid] = lss;
    __syncthreads();
    for (int s = 128; s > 0; s >>= 1) {
        if (tid < s) red[tid] += red[tid + s];
        __syncthreads();
    }
    const float var = red[0] / (float)(n - 1);
    const float inv = 1.0f / (sqrtf(var) + STD_EPSF);

    for (int t = tid; t < Tpad; t += 256) {
        float o;
        if (t < n)      o = (sx[t] - mean) * inv;
        else if (t < T) o = 0.0f;
        else            o = BLANKF;
        row[t] = o;
    }
}

/* ------------------------------------------------------------------ K5:
 * seq_len tail (flattened after the (B,80,Tpad) block).
 * rem == B    -> output dtype float32, seq cast to float
 * rem == 2*B  -> raw int64 bits occupying 2 fp32 slots each
 */
__global__ void k_tail(float* __restrict__ out, const int* __restrict__ xn32,
                       int B, size_t mainElems, int rem) {
    int b = threadIdx.x + blockIdx.x * blockDim.x;
    if (b >= B) return;
    long long seq = (long long)load_seqlen(xn32, b);
    if (rem == B) {
        out[mainElems + b] = (float)seq;
    } else if (rem == 2 * B) {
        ((long long*)(out + mainElems))[b] = seq;
    } else if (rem > 0 && b == 0) {
        for (int i = 0; i < rem && i < B; i++)
            out[mainElems + i] = (float)load_seqlen(xn32, i);
    }
}

extern "C" void kernel_launch(void* const* d_in, const int* in_sizes, int n_in,
                              void* d_out, int out_size) {
    const float* x    = (const float*)d_in[0];
    const int*   xn32 = (const int*)d_in[1];
    const float* fb   = (const float*)d_in[2];

    const int B    = in_sizes[1];
    const int L    = in_sizes[0] / B;
    const int Lp   = L + NFFT;
    const int T    = L / HOP + 1;
    const int Tpad = ((T + 7) / 8) * 8;

    float* out = (float*)d_out;

    k_preemph<<<2048, 256>>>(x, B, L, Lp);
    k_fbpad<<<(NMELS * FB_PITCH + 255) / 256, 256>>>(fb);
    k_fft<<<dim3((T + 1) / 2, B), 256>>>(Lp, T);
    k_mel<<<dim3((T + TT - 1) / TT, B), 256>>>(out, B, T, Tpad);
    k_norm<<<dim3(NMELS, B), 256>>>(out, xn32, T, Tpad);

    size_t mainE = (size_t)B * NMELS * Tpad;
    int rem = out_size - (int)mainE;
    if (rem > 0) k_tail<<<1, 256>>>(out, xn32, B, mainE, rem);
}

// round 3
// speedup vs baseline: 1.0417x; 1.0417x over previous
#include <cuda_runtime.h>
#include <math.h>

#define HOP      160
#define NFFT     512
#define WINLEN   320
#define NMELS    80
#define NBINS    257
#define PREEMPH  0.97f
#define LOG_EPSF 5.9604644775390625e-08f   /* 2^-24 */
#define STD_EPSF 1e-5f
#define BLANKF   27.0f

#define MAXB   32
#define MAXL   240000
#define MAXLP  (MAXL + NFFT)       /* 240512 */
#define MAXT   (MAXL / HOP + 1)    /* 1501 */

#define WTAPS    32                /* padded taps per mel row (max real width ~23+3) */
#define SP_PITCH 268               /* frame row pitch in smem: >= max(start4)+32, mult of 4 */
#define TT       32                /* frames per mel tile */
#define FPB      8                 /* frames per fft block */

__device__ float g_ypad[MAXB * MAXLP];
__device__ float g_power[(size_t)MAXB * MAXT * NBINS];
__device__ __align__(16) float g_mw[NMELS * WTAPS];   /* narrow dense weights */
__device__ int   g_mstart[NMELS];                     /* aligned-down start bin */
__device__ float2 g_tw[NFFT / 2];                     /* fft twiddles */
__device__ float  g_win[NFFT];                        /* padded hann window */

/* xn may be int32 (JAX default) or int64; lengths >= 160000 so word[1]==0
 * implies int64 layout. Only in-bounds words are read either way. */
__device__ __forceinline__ int load_seqlen(const int* __restrict__ xn32, int b) {
    int is64 = (xn32[1] == 0);
    int v = is64 ? xn32[2 * b] : xn32[b];
    return v / HOP + 1;
}

/* ------------------------------------------------------------------ K0:
 * one-block init: twiddles, window, sparse->narrow filterbank repack.
 */
__global__ void k_tables(const float* __restrict__ fb) {
    int tid = threadIdx.x;   /* 256 */
    if (tid < NFFT / 2) {
        float s, c;
        sincosf((float)tid * (-6.283185307179586f / 512.0f), &s, &c);
        g_tw[tid] = make_float2(c, s);
    }
    for (int i = tid; i < NFFT; i += 256) {
        float w = 0.0f;
        if (i >= (NFFT - WINLEN) / 2 && i < (NFFT + WINLEN) / 2) {
            float ph = (float)(i - (NFFT - WINLEN) / 2) * (6.283185307179586f / (float)WINLEN);
            w = 0.5f - 0.5f * cosf(ph);
        }
        g_win[i] = w;
    }
    if (tid < NMELS) {
        const float* row = fb + tid * NBINS;
        int f0 = -1, f1 = 0;
        for (int k = 0; k < NBINS; k++) {
            if (row[k] != 0.0f) { if (f0 < 0) f0 = k; f1 = k; }
        }
        if (f0 < 0) { f0 = 0; f1 = 0; }
        int s4 = f0 & ~3;
        if (s4 > NBINS - WTAPS + 3) s4 = (NBINS - WTAPS + 3) & ~3;  /* keep taps in pitch */
        g_mstart[tid] = s4;
        for (int j = 0; j < WTAPS; j++) {
            int k = s4 + j;
            g_mw[tid * WTAPS + j] = (k >= f0 && k <= f1) ? row[k] : 0.0f;
        }
    }
}

/* ------------------------------------------------------------------ K1:
 * preemphasis + reflect pad:  ypad[b][i] = y[reflect(i-256)]
 */
__global__ void k_preemph(const float* __restrict__ x, int B, int L, int Lp) {
    int total = B * Lp;
    for (int gid = blockIdx.x * blockDim.x + threadIdx.x; gid < total;
         gid += gridDim.x * blockDim.x) {
        int b = gid / Lp;
        int i = gid - b * Lp;
        int j = i - NFFT / 2;
        int jj = (j < 0) ? -j : ((j >= L) ? (2 * L - 2 - j) : j);
        const float* xb = x + (size_t)b * L;
        float v = (jj == 0) ? xb[0] : (xb[jj] - PREEMPH * xb[jj - 1]);
        g_ypad[(size_t)b * Lp + i] = v;
    }
}

/* ------------------------------------------------------------------ K2:
 * 8 frames per block: 4 packed real-pair 512-pt DIF FFTs, tables from smem.
 */
__global__ void k_fft(int Lp, int T) {
    __shared__ float zr[NFFT], zi[NFFT];
    __shared__ float2 tw[NFFT / 2];
    __shared__ float wwin[NFFT];

    const int tid = threadIdx.x;           /* 256 */
    const int b   = blockIdx.y;
    const int tbase = blockIdx.x * FPB;

    tw[tid] = g_tw[tid];
    wwin[tid]       = g_win[tid];
    wwin[tid + 256] = g_win[tid + 256];

    const float* yb = g_ypad + (size_t)b * Lp;

    for (int pp = 0; pp < FPB / 2; pp++) {
        const int t0 = tbase + 2 * pp;
        const int t1 = t0 + 1;
        if (t0 >= T) break;
        const bool has1 = (t1 < T);

        __syncthreads();   /* previous unpack reads / table stores done */

        for (int i = tid; i < NFFT; i += 256) {
            float w = wwin[i];
            float a  = yb[t0 * HOP + i] * w;
            float bb = has1 ? (yb[t1 * HOP + i] * w) : 0.0f;
            zr[i] = a;
            zi[i] = bb;
        }
        __syncthreads();

        #pragma unroll
        for (int s = 0; s < 9; s++) {
            int h  = 256 >> s;
            int p  = tid & (h - 1);
            int i0 = ((tid >> (8 - s)) << (9 - s)) + p;
            int i1 = i0 + h;
            float2 c = tw[p << s];
            float ur = zr[i0], ui = zi[i0];
            float vr = zr[i1], vi = zi[i1];
            float dr = ur - vr, di = ui - vi;
            zr[i0] = ur + vr;
            zi[i0] = ui + vi;
            zr[i1] = dr * c.x - di * c.y;
            zi[i1] = dr * c.y + di * c.x;
            __syncthreads();
        }

        for (int k = tid; k <= NFFT / 2; k += 256) {
            int kn = (NFFT - k) & (NFFT - 1);
            int r1 = __brev(k)  >> 23;
            int r2 = __brev(kn) >> 23;
            float z1r = zr[r1], z1i = zi[r1];
            float z2r = zr[r2], z2i = zi[r2];
            float Ar = 0.5f * (z1r + z2r);
            float Ai = 0.5f * (z1i - z2i);
            float Br = 0.5f * (z1i + z2i);
            float Bi = 0.5f * (z2r - z1r);
            size_t base = ((size_t)b * T + t0) * NBINS;
            g_power[base + k] = Ar * Ar + Ai * Ai;
            if (has1) g_power[base + NBINS + k] = Br * Br + Bi * Bi;
        }
    }
}

/* ------------------------------------------------------------------ K3:
 * sparse mel projection + log.  Block: 32 frames; warp = 32 frames (lane=frame),
 * each warp handles 10 mels with 32 narrow taps each. LDS.128 conflict-free.
 */
__global__ void k_mel(float* __restrict__ out, int T, int Tpad) {
    __shared__ float sp[TT * SP_PITCH];

    const int tid   = threadIdx.x;        /* 256 */
    const int b     = blockIdx.y;
    const int tbase = blockIdx.x * TT;

    for (int i = tid; i < TT * SP_PITCH; i += 256) {
        int tt = i / SP_PITCH;
        int k  = i - tt * SP_PITCH;
        int t  = tbase + tt;
        float v = 0.0f;
        if (t < T && k < NBINS) v = g_power[((size_t)b * T + t) * NBINS + k];
        sp[i] = v;
    }
    __syncthreads();

    const int wid  = tid >> 5;
    const int lane = tid & 31;
    const int t    = tbase + lane;
    const bool valid = (t < T);
    const float* prow = sp + lane * SP_PITCH;

    for (int r = 0; r < 10; r++) {
        int m = wid * 10 + r;
        int s4 = g_mstart[m];
        const float4* wv = (const float4*)(g_mw + m * WTAPS);
        const float4* pv = (const float4*)(prow + s4);
        float acc = 0.0f;
        #pragma unroll
        for (int q = 0; q < WTAPS / 4; q++) {
            float4 f = __ldg(&wv[q]);
            float4 p = pv[q];
            acc += f.x * p.x + f.y * p.y + f.z * p.z + f.w * p.w;
        }
        if (valid)
            out[((size_t)b * NMELS + m) * Tpad + t] = __logf(acc + LOG_EPSF);
    }
}

/* ------------------------------------------------------------------ K4:
 * per-(b,m) masked mean/var normalization, in-place, BLANK pad.
 */
__global__ void k_norm(float* __restrict__ out, const int* __restrict__ xn32,
                       int T, int Tpad) {
    __shared__ float sx[1504];
    __shared__ float red[256];

    const int tid = threadIdx.x;          /* 256 */
    const int m   = blockIdx.x;
    const int b   = blockIdx.y;

    int n = load_seqlen(xn32, b);
    if (n < 2) n = 2;
    if (n > T) n = T;

    float* row = out + ((size_t)b * NMELS + m) * Tpad;

    float lsum = 0.0f;
    for (int t = tid; t < T; t += 256) {
        float v = row[t];
        sx[t] = v;
        if (t < n) lsum += v;
    }
    red[tid] = lsum;
    __syncthreads();
    for (int s = 128; s > 0; s >>= 1) {
        if (tid < s) red[tid] += red[tid + s];
        __syncthreads();
    }
    const float mean = red[0] / (float)n;
    __syncthreads();

    float lss = 0.0f;
    for (int t = tid; t < n; t += 256) {
        float d = sx[t] - mean;
        lss += d * d;
    }
    red[tid] = lss;
    __syncthreads();
    for (int s = 128; s > 0; s >>= 1) {
        if (tid < s) red[tid] += red[tid + s];
        __syncthreads();
    }
    const float var = red[0] / (float)(n - 1);
    const float inv = 1.0f / (sqrtf(var) + STD_EPSF);

    for (int t = tid; t < Tpad; t += 256) {
        float o;
        if (t < n)      o = (sx[t] - mean) * inv;
        else if (t < T) o = 0.0f;
        else            o = BLANKF;
        row[t] = o;
    }
}

/* ------------------------------------------------------------------ K5: seq_len tail */
__global__ void k_tail(float* __restrict__ out, const int* __restrict__ xn32,
                       int B, size_t mainElems, int rem) {
    int b = threadIdx.x + blockIdx.x * blockDim.x;
    if (b >= B) return;
    long long seq = (long long)load_seqlen(xn32, b);
    if (rem == B) {
        out[mainElems + b] = (float)seq;
    } else if (rem == 2 * B) {
        ((long long*)(out + mainElems))[b] = seq;
    } else if (rem > 0 && b == 0) {
        for (int i = 0; i < rem && i < B; i++)
            out[mainElems + i] = (float)load_seqlen(xn32, i);
    }
}

extern "C" void kernel_launch(void* const* d_in, const int* in_sizes, int n_in,
                              void* d_out, int out_size) {
    const float* x    = (const float*)d_in[0];
    const int*   xn32 = (const int*)d_in[1];
    const float* fb   = (const float*)d_in[2];

    const int B    = in_sizes[1];
    const int L    = in_sizes[0] / B;
    const int Lp   = L + NFFT;
    const int T    = L / HOP + 1;
    const int Tpad = ((T + 7) / 8) * 8;

    float* out = (float*)d_out;

    k_tables<<<1, 256>>>(fb);
    k_preemph<<<2048, 256>>>(x, B, L, Lp);
    k_fft<<<dim3((T + FPB - 1) / FPB, B), 256>>>(Lp, T);
    k_mel<<<dim3((T + TT - 1) / TT, B), 256>>>(out, T, Tpad);
    k_norm<<<dim3(NMELS, B), 256>>>(out, xn32, T, Tpad);

    size_t mainE = (size_t)B * NMELS * Tpad;
    int rem = out_size - (int)mainE;
    if (rem > 0) k_tail<<<1, 256>>>(out, xn32, B, mainE, rem);
}

// round 4
// speedup vs baseline: 1.1036x; 1.0595x over previous
#include <cuda_runtime.h>
#include <math.h>

#define HOP      160
#define NFFT     512
#define WINLEN   320
#define NMELS    80
#define NBINS    257
#define PREEMPH  0.97f
#define LOG_EPSF 5.9604644775390625e-08f   /* 2^-24 */
#define STD_EPSF 1e-5f
#define BLANKF   27.0f

#define WTAPS    32                /* padded taps per mel row */
#define FPB      8                 /* frames per block */
#define PB_PITCH 9                 /* pbuf[bin][frame] pitch (odd-ish -> no conflicts) */
#define PB_BINS  260               /* s4max(228)+32 = 260 */
#define YBUF     ((FPB - 1) * HOP + NFFT)   /* 1632 samples staged per block */

__device__ __align__(16) float g_mw[NMELS * WTAPS];
__device__ int    g_mstart[NMELS];
__device__ float2 g_tw[NFFT / 2];
__device__ float  g_win[NFFT];

/* xn may be int32 (JAX default) or int64; lengths >= 160000 so word[1]==0
 * implies int64 layout. Only in-bounds words are read either way. */
__device__ __forceinline__ int load_seqlen(const int* __restrict__ xn32, int b) {
    int is64 = (xn32[1] == 0);
    int v = is64 ? xn32[2 * b] : xn32[b];
    return v / HOP + 1;
}

/* ------------------------------------------------------------------ K0:
 * parallel tables. blocks 0..79: mel row repack; 80: twiddles; 81: window.
 */
__global__ void k_tables(const float* __restrict__ fb) {
    const int m   = blockIdx.x;
    const int tid = threadIdx.x;   /* 64 */

    if (m == NMELS) {
        for (int i = tid; i < NFFT / 2; i += 64) {
            float s, c;
            sincosf((float)i * (-6.283185307179586f / 512.0f), &s, &c);
            g_tw[i] = make_float2(c, s);
        }
        return;
    }
    if (m == NMELS + 1) {
        for (int i = tid; i < NFFT; i += 64) {
            float w = 0.0f;
            if (i >= (NFFT - WINLEN) / 2 && i < (NFFT + WINLEN) / 2) {
                float ph = (float)(i - (NFFT - WINLEN) / 2) *
                           (6.283185307179586f / (float)WINLEN);
                w = 0.5f - 0.5f * cosf(ph);
            }
            g_win[i] = w;
        }
        return;
    }

    __shared__ int sf0, sf1;
    if (tid == 0) { sf0 = NBINS; sf1 = -1; }
    __syncthreads();

    const float* row = fb + m * NBINS;
    int f0 = NBINS, f1 = -1;
    for (int k = tid; k < NBINS; k += 64) {
        if (row[k] != 0.0f) { if (k < f0) f0 = k; if (k > f1) f1 = k; }
    }
    atomicMin(&sf0, f0);
    atomicMax(&sf1, f1);
    __syncthreads();
    f0 = sf0; f1 = sf1;
    if (f1 < 0) { f0 = 0; f1 = 0; }

    int s4 = f0 & ~3;
    if (s4 > NBINS - WTAPS + 3) s4 = (NBINS - WTAPS + 3) & ~3;   /* 228 */
    if (tid == 0) g_mstart[m] = s4;
    for (int j = tid; j < WTAPS; j += 64) {
        int k = s4 + j;
        g_mw[m * WTAPS + j] = (k >= f0 && k <= f1 && k < NBINS) ? row[k] : 0.0f;
    }
}

/* ------------------------------------------------------------------ K1:
 * fused preemph + reflect + window + 4 pair-FFTs + sparse mel + log.
 * One block = 8 frames of one batch. 256 threads.
 */
__global__ void k_fftmel(const float* __restrict__ x, float* __restrict__ out,
                         int L, int T, int Tpad) {
    __shared__ float ybuf[YBUF];
    __shared__ float zr[NFFT], zi[NFFT];
    __shared__ float2 tw[NFFT / 2];
    __shared__ float wwin[NFFT];
    __shared__ float pbuf[PB_BINS * PB_PITCH];

    const int tid   = threadIdx.x;          /* 256 */
    const int b     = blockIdx.y;
    const int tbase = blockIdx.x * FPB;

    /* tables to smem */
    tw[tid] = g_tw[tid];
    wwin[tid]       = g_win[tid];
    wwin[tid + 256] = g_win[tid + 256];

    /* zero the mel-tap tail bins (rows 257..259, all frame cols) */
    if (tid < (PB_BINS - NBINS) * PB_PITCH)
        pbuf[NBINS * PB_PITCH + tid] = 0.0f;

    /* stage preemphasized, reflect-padded span into smem */
    const float* xb = x + (size_t)b * L;
    const int jbase = tbase * HOP - NFFT / 2;
    for (int i = tid; i < YBUF; i += 256) {
        int j = jbase + i;
        int jj = (j < 0) ? -j : ((j >= L) ? (2 * L - 2 - j) : j);
        ybuf[i] = (jj == 0) ? xb[0] : (xb[jj] - PREEMPH * xb[jj - 1]);
    }
    __syncthreads();

    const int wq = tid >> 5;
    const int l  = tid & 31;

    for (int pp = 0; pp < FPB / 2; pp++) {
        const int t0 = tbase + 2 * pp;
        const int t1 = t0 + 1;
        const bool has0 = (t0 < T);
        const bool has1 = (t1 < T);

        /* windowed frame pair -> packed complex */
        for (int i = tid; i < NFFT; i += 256) {
            float w  = wwin[i];
            int off  = 2 * pp * HOP + i;
            zr[i] = has0 ? ybuf[off] * w : 0.0f;
            zi[i] = has1 ? ybuf[off + HOP] * w : 0.0f;
        }
        __syncthreads();

        /* stages 0..2: cross-warp */
        #pragma unroll
        for (int s = 0; s < 3; s++) {
            int h  = 256 >> s;
            int p  = tid & (h - 1);
            int i0 = ((tid >> (8 - s)) << (9 - s)) + p;
            int i1 = i0 + h;
            float2 c = tw[p << s];
            float ur = zr[i0], ui = zi[i0];
            float vr = zr[i1], vi = zi[i1];
            float dr = ur - vr, di = ui - vi;
            zr[i0] = ur + vr;
            zi[i0] = ui + vi;
            zr[i1] = dr * c.x - di * c.y;
            zi[i1] = dr * c.y + di * c.x;
            __syncthreads();
        }

        /* stages 3..8: each warp owns a contiguous 64-pt chunk */
        #pragma unroll
        for (int s = 3; s < 9; s++) {
            int h  = 256 >> s;
            int p  = l & (h - 1);
            int i0 = wq * 64 + ((l >> (8 - s)) << (9 - s)) + p;
            int i1 = i0 + h;
            float2 c = tw[p << s];
            float ur = zr[i0], ui = zi[i0];
            float vr = zr[i1], vi = zi[i1];
            float dr = ur - vr, di = ui - vi;
            zr[i0] = ur + vr;
            zi[i0] = ui + vi;
            zr[i1] = dr * c.x - di * c.y;
            zi[i1] = dr * c.y + di * c.x;
            __syncwarp();
        }
        __syncthreads();

        /* unpack packed real pair -> power rows of pbuf (transposed) */
        for (int k = tid; k <= NFFT / 2; k += 256) {
            int kn = (NFFT - k) & (NFFT - 1);
            int r1 = __brev(k)  >> 23;
            int r2 = __brev(kn) >> 23;
            float z1r = zr[r1], z1i = zi[r1];
            float z2r = zr[r2], z2i = zi[r2];
            float Ar = 0.5f * (z1r + z2r);
            float Ai = 0.5f * (z1i - z2i);
            float Br = 0.5f * (z1i + z2i);
            float Bi = 0.5f * (z2r - z1r);
            pbuf[k * PB_PITCH + 2 * pp]     = Ar * Ar + Ai * Ai;
            pbuf[k * PB_PITCH + 2 * pp + 1] = Br * Br + Bi * Bi;
        }
        __syncthreads();
    }

    /* sparse mel + log: 640 outputs (80 mels x 8 frames) */
    for (int oi = tid; oi < NMELS * FPB; oi += 256) {
        int m    = oi >> 3;
        int tloc = oi & 7;
        int s4   = g_mstart[m];
        const float* wm = g_mw + m * WTAPS;
        const float* pv = pbuf + s4 * PB_PITCH + tloc;
        float acc = 0.0f;
        #pragma unroll
        for (int j = 0; j < WTAPS; j++)
            acc += __ldg(&wm[j]) * pv[j * PB_PITCH];
        int t = tbase + tloc;
        if (t < T)
            out[((size_t)b * NMELS + m) * Tpad + t] = __logf(acc + LOG_EPSF);
    }
}

/* ------------------------------------------------------------------ K2:
 * per-(b,m) masked mean/var normalization, in-place, BLANK pad.
 */
__global__ void k_norm(float* __restrict__ out, const int* __restrict__ xn32,
                       int T, int Tpad) {
    __shared__ float sx[1504];
    __shared__ float red[256];

    const int tid = threadIdx.x;          /* 256 */
    const int m   = blockIdx.x;
    const int b   = blockIdx.y;

    int n = load_seqlen(xn32, b);
    if (n < 2) n = 2;
    if (n > T) n = T;

    float* row = out + ((size_t)b * NMELS + m) * Tpad;

    float lsum = 0.0f;
    for (int t = tid; t < T; t += 256) {
        float v = row[t];
        sx[t] = v;
        if (t < n) lsum += v;
    }
    red[tid] = lsum;
    __syncthreads();
    for (int s = 128; s > 0; s >>= 1) {
        if (tid < s) red[tid] += red[tid + s];
        __syncthreads();
    }
    const float mean = red[0] / (float)n;
    __syncthreads();

    float lss = 0.0f;
    for (int t = tid; t < n; t += 256) {
        float d = sx[t] - mean;
        lss += d * d;
    }
    red[tid] = lss;
    __syncthreads();
    for (int s = 128; s > 0; s >>= 1) {
        if (tid < s) red[tid] += red[tid + s];
        __syncthreads();
    }
    const float var = red[0] / (float)(n - 1);
    const float inv = 1.0f / (sqrtf(var) + STD_EPSF);

    for (int t = tid; t < Tpad; t += 256) {
        float o;
        if (t < n)      o = (sx[t] - mean) * inv;
        else if (t < T) o = 0.0f;
        else            o = BLANKF;
        row[t] = o;
    }
}

/* ------------------------------------------------------------------ K3: seq_len tail */
__global__ void k_tail(float* __restrict__ out, const int* __restrict__ xn32,
                       int B, size_t mainElems, int rem) {
    int b = threadIdx.x + blockIdx.x * blockDim.x;
    if (b >= B) return;
    long long seq = (long long)load_seqlen(xn32, b);
    if (rem == B) {
        out[mainElems + b] = (float)seq;
    } else if (rem == 2 * B) {
        ((long long*)(out + mainElems))[b] = seq;
    } else if (rem > 0 && b == 0) {
        for (int i = 0; i < rem && i < B; i++)
            out[mainElems + i] = (float)load_seqlen(xn32, i);
    }
}

extern "C" void kernel_launch(void* const* d_in, const int* in_sizes, int n_in,
                              void* d_out, int out_size) {
    const float* x    = (const float*)d_in[0];
    const int*   xn32 = (const int*)d_in[1];
    const float* fb   = (const float*)d_in[2];

    const int B    = in_sizes[1];
    const int L    = in_sizes[0] / B;
    const int T    = L / HOP + 1;
    const int Tpad = ((T + 7) / 8) * 8;

    float* out = (float*)d_out;

    k_tables<<<NMELS + 2, 64>>>(fb);
    k_fftmel<<<dim3((T + FPB - 1) / FPB, B), 256>>>(x, out, L, T, Tpad);
    k_norm<<<dim3(NMELS, B), 256>>>(out, xn32, T, Tpad);

    size_t mainE = (size_t)B * NMELS * Tpad;
    int rem = out_size - (int)mainE;
    if (rem > 0) k_tail<<<1, 256>>>(out, xn32, B, mainE, rem);
}

// round 5
// speedup vs baseline: 2.0760x; 1.8810x over previous
#include <cuda_runtime.h>
#include <math.h>

#define HOP      160
#define NFFT     512
#define WINLEN   320
#define NMELS    80
#define NBINS    257
#define PREEMPH  0.97f
#define LOG_EPSF 5.9604644775390625e-08f   /* 2^-24 */
#define STD_EPSF 1e-5f
#define BLANKF   27.0f

#define WTAPS    32                 /* padded taps per mel row */
#define FPB      16                 /* frames per block (8 warps x 1 pair) */
#define PB_PITCH 17                 /* pbuf[bin][frame] pitch */
#define PB_BINS  260                /* s4max(228)+32 */
#define YBUF     ((FPB - 1) * HOP + NFFT)   /* 2912 samples staged per block */

/* dynamic smem layout (floats):
 * [0,512)            tw       (256 float2)
 * [512,8704)         zsh      (8 warps x (zr512 + zi512))
 * [8704,11616)       ybuf     (2912)
 * [11616,12128)      wwin     (512)
 * [12128,16548)      pbuf     (260*17)
 */
#define SM_TW    0
#define SM_ZSH   512
#define SM_YBUF  (SM_ZSH + 8 * 1024)
#define SM_WWIN  (SM_YBUF + YBUF)
#define SM_PBUF  (SM_WWIN + NFFT)
#define SM_FLOATS (SM_PBUF + PB_BINS * PB_PITCH)
#define SMEM_BYTES (SM_FLOATS * 4)

__device__ __align__(16) float g_mw[NMELS * WTAPS];
__device__ int    g_mstart[NMELS];
__device__ float2 g_tw[NFFT / 2];
__device__ float  g_win[NFFT];

/* xn may be int32 (JAX default) or int64; lengths >= 160000 so word[1]==0
 * implies int64 layout. Only in-bounds words are read either way. */
__device__ __forceinline__ int load_seqlen(const int* __restrict__ xn32, int b) {
    int is64 = (xn32[1] == 0);
    int v = is64 ? xn32[2 * b] : xn32[b];
    return v / HOP + 1;
}

/* ------------------------------------------------------------------ K0:
 * parallel tables. blocks 0..79: mel row repack; 80: twiddles; 81: window.
 */
__global__ void k_tables(const float* __restrict__ fb) {
    const int m   = blockIdx.x;
    const int tid = threadIdx.x;   /* 64 */

    if (m == NMELS) {
        for (int i = tid; i < NFFT / 2; i += 64) {
            float s, c;
            sincosf((float)i * (-6.283185307179586f / 512.0f), &s, &c);
            g_tw[i] = make_float2(c, s);
        }
        return;
    }
    if (m == NMELS + 1) {
        for (int i = tid; i < NFFT; i += 64) {
            float w = 0.0f;
            if (i >= (NFFT - WINLEN) / 2 && i < (NFFT + WINLEN) / 2) {
                float ph = (float)(i - (NFFT - WINLEN) / 2) *
                           (6.283185307179586f / (float)WINLEN);
                w = 0.5f - 0.5f * cosf(ph);
            }
            g_win[i] = w;
        }
        return;
    }

    __shared__ int sf0, sf1;
    if (tid == 0) { sf0 = NBINS; sf1 = -1; }
    __syncthreads();

    const float* row = fb + m * NBINS;
    int f0 = NBINS, f1 = -1;
    for (int k = tid; k < NBINS; k += 64) {
        if (row[k] != 0.0f) { if (k < f0) f0 = k; if (k > f1) f1 = k; }
    }
    atomicMin(&sf0, f0);
    atomicMax(&sf1, f1);
    __syncthreads();
    f0 = sf0; f1 = sf1;
    if (f1 < 0) { f0 = 0; f1 = 0; }

    int s4 = f0 & ~3;
    if (s4 > NBINS - WTAPS + 3) s4 = (NBINS - WTAPS + 3) & ~3;   /* 228 */
    if (tid == 0) g_mstart[m] = s4;
    for (int j = tid; j < WTAPS; j += 64) {
        int k = s4 + j;
        g_mw[m * WTAPS + j] = (k >= f0 && k <= f1 && k < NBINS) ? row[k] : 0.0f;
    }
}

/* ------------------------------------------------------------------ K1:
 * fused preemph + reflect + window + warp-register pair-FFT + sparse mel.
 * 256 threads, 8 warps, 16 frames per block; one pair-FFT per warp,
 * each thread holds 16 complex points in registers.
 */
__global__ void __launch_bounds__(256)
k_fftmel(const float* __restrict__ x, float* __restrict__ out,
         int L, int T, int Tpad) {
    extern __shared__ float sm[];
    float2* tw  = (float2*)(sm + SM_TW);
    float* zsh  = sm + SM_ZSH;
    float* ybuf = sm + SM_YBUF;
    float* wwin = sm + SM_WWIN;
    float* pbuf = sm + SM_PBUF;

    const int tid   = threadIdx.x;
    const int w     = tid >> 5;
    const int t     = tid & 31;
    const int b     = blockIdx.y;
    const int tbase = blockIdx.x * FPB;

    /* tables to smem */
    tw[tid] = g_tw[tid];
    wwin[tid]       = g_win[tid];
    wwin[tid + 256] = g_win[tid + 256];

    /* zero mel-tap tail bins (rows 257..259) */
    if (tid < (PB_BINS - NBINS) * PB_PITCH)
        pbuf[NBINS * PB_PITCH + tid] = 0.0f;

    /* stage preemphasized, reflect-padded span */
    const float* xb = x + (size_t)b * L;
    const int jbase = tbase * HOP - NFFT / 2;
    for (int i = tid; i < YBUF; i += 256) {
        int j = jbase + i;
        int jj = (j < 0) ? -j : ((j >= L) ? (2 * L - 2 - j) : j);
        ybuf[i] = (jj == 0) ? xb[0] : (xb[jj] - PREEMPH * xb[jj - 1]);
    }
    __syncthreads();

    const int t0   = tbase + 2 * w;
    const bool has0 = (t0 < T);
    const bool has1 = (t0 + 1 < T);

    float Rr[16], Ri[16];
    const int base = 2 * w * HOP;
    #pragma unroll
    for (int q = 0; q < 16; q++) {
        int i = q * 32 + t;
        float wv = wwin[i];
        Rr[q] = has0 ? ybuf[base + i] * wv : 0.0f;
        Ri[q] = has1 ? ybuf[base + HOP + i] * wv : 0.0f;
    }

    /* stages 0..3: within-thread butterflies (partner is another q) */
    #pragma unroll
    for (int s = 0; s < 4; s++) {
        const int qh = 8 >> s;
        #pragma unroll
        for (int qb = 0; qb < 16; qb++) {
            if (!(qb & qh)) {
                const int q1 = qb + qh;
                int idx = (((qb & (qh - 1)) * 32 + t) << s);
                float2 c = tw[idx];
                float ur = Rr[qb], ui = Ri[qb];
                float vr = Rr[q1], vi = Ri[q1];
                float dr = ur - vr, di = ui - vi;
                Rr[qb] = ur + vr;  Ri[qb] = ui + vi;
                Rr[q1] = dr * c.x - di * c.y;
                Ri[q1] = dr * c.y + di * c.x;
            }
        }
    }

    /* stages 4..8: cross-lane via shfl_xor; twiddle depends only on lane */
    #pragma unroll
    for (int s = 4; s < 9; s++) {
        const int hh = 256 >> s;           /* 16,8,4,2,1 */
        float2 c = tw[(t & (hh - 1)) << s];
        const bool up = (t & hh) != 0;
        #pragma unroll
        for (int q = 0; q < 16; q++) {
            float pr = __shfl_xor_sync(0xffffffffu, Rr[q], hh);
            float pi = __shfl_xor_sync(0xffffffffu, Ri[q], hh);
            if (!up) {
                Rr[q] += pr;  Ri[q] += pi;
            } else {
                float dr = pr - Rr[q], di = pi - Ri[q];
                Rr[q] = dr * c.x - di * c.y;
                Ri[q] = dr * c.y + di * c.x;
            }
        }
    }

    /* dump bit-reversed-position data to this warp's smem strip */
    float* zr = zsh + w * 1024;
    float* zi = zr + 512;
    #pragma unroll
    for (int q = 0; q < 16; q++) {
        zr[q * 32 + t] = Rr[q];
        zi[q * 32 + t] = Ri[q];
    }
    __syncwarp();

    /* unpack packed real pair -> transposed power columns 2w, 2w+1 */
    for (int k = t; k <= NFFT / 2; k += 32) {
        int kn = (NFFT - k) & (NFFT - 1);
        int r1 = __brev(k)  >> 23;
        int r2 = __brev(kn) >> 23;
        float z1r = zr[r1], z1i = zi[r1];
        float z2r = zr[r2], z2i = zi[r2];
        float Ar = 0.5f * (z1r + z2r);
        float Ai = 0.5f * (z1i - z2i);
        float Br = 0.5f * (z1i + z2i);
        float Bi = 0.5f * (z2r - z1r);
        pbuf[k * PB_PITCH + 2 * w]     = Ar * Ar + Ai * Ai;
        pbuf[k * PB_PITCH + 2 * w + 1] = Br * Br + Bi * Bi;
    }
    __syncthreads();

    /* sparse mel + log: 1280 outputs (80 mels x 16 frames) */
    for (int oi = tid; oi < NMELS * FPB; oi += 256) {
        int m    = oi >> 4;
        int tloc = oi & 15;
        int s4   = g_mstart[m];
        const float* wm = g_mw + m * WTAPS;
        const float* pv = pbuf + s4 * PB_PITCH + tloc;
        float acc = 0.0f;
        #pragma unroll
        for (int j = 0; j < WTAPS; j++)
            acc += __ldg(&wm[j]) * pv[j * PB_PITCH];
        int tt = tbase + tloc;
        if (tt < T)
            out[((size_t)b * NMELS + m) * Tpad + tt] = __logf(acc + LOG_EPSF);
    }
}

/* ------------------------------------------------------------------ K2:
 * per-(b,m) masked mean/var normalization, in-place, BLANK pad.
 * Block (m==0) thread 0 also writes batch b's seq_len tail entry.
 */
__global__ void k_norm(float* __restrict__ out, const int* __restrict__ xn32,
                       int T, int Tpad, size_t mainElems, int rem, int B) {
    __shared__ float sx[1504];
    __shared__ float red[256];

    const int tid = threadIdx.x;          /* 256 */
    const int m   = blockIdx.x;
    const int b   = blockIdx.y;

    const int seq = load_seqlen(xn32, b);
    int n = seq;
    if (n < 2) n = 2;
    if (n > T) n = T;

    if (m == 0 && tid == 0 && rem > 0) {
        if (rem == B) {
            out[mainElems + b] = (float)seq;
        } else if (rem == 2 * B) {
            ((long long*)(out + mainElems))[b] = (long long)seq;
        } else if (b == 0) {
            for (int i = 0; i < rem && i < B; i++)
                out[mainElems + i] = (float)load_seqlen(xn32, i);
        }
    }

    float* row = out + ((size_t)b * NMELS + m) * Tpad;

    float lsum = 0.0f;
    for (int t = tid; t < T; t += 256) {
        float v = row[t];
        sx[t] = v;
        if (t < n) lsum += v;
    }
    red[tid] = lsum;
    __syncthreads();
    for (int s = 128; s > 0; s >>= 1) {
        if (tid < s) red[tid] += red[tid + s];
        __syncthreads();
    }
    const float mean = red[0] / (float)n;
    __syncthreads();

    float lss = 0.0f;
    for (int t = tid; t < n; t += 256) {
        float d = sx[t] - mean;
        lss += d * d;
    }
    red[tid] = lss;
    __syncthreads();
    for (int s = 128; s > 0; s >>= 1) {
        if (tid < s) red[tid] += red[tid + s];
        __syncthreads();
    }
    const float var = red[0] / (float)(n - 1);
    const float inv = 1.0f / (sqrtf(var) + STD_EPSF);

    for (int t = tid; t < Tpad; t += 256) {
        float o;
        if (t < n)      o = (sx[t] - mean) * inv;
        else if (t < T) o = 0.0f;
        else            o = BLANKF;
        row[t] = o;
    }
}

extern "C" void kernel_launch(void* const* d_in, const int* in_sizes, int n_in,
                              void* d_out, int out_size) {
    const float* x    = (const float*)d_in[0];
    const int*   xn32 = (const int*)d_in[1];
    const float* fb   = (const float*)d_in[2];

    const int B    = in_sizes[1];
    const int L    = in_sizes[0] / B;
    const int T    = L / HOP + 1;
    const int Tpad = ((T + 7) / 8) * 8;

    float* out = (float*)d_out;

    cudaFuncSetAttribute(k_fftmel, cudaFuncAttributeMaxDynamicSharedMemorySize,
                         SMEM_BYTES);

    k_tables<<<NMELS + 2, 64>>>(fb);
    k_fftmel<<<dim3((T + FPB - 1) / FPB, B), 256, SMEM_BYTES>>>(x, out, L, T, Tpad);

    size_t mainE = (size_t)B * NMELS * Tpad;
    int rem = out_size - (int)mainE;
    k_norm<<<dim3(NMELS, B), 256>>>(out, xn32, T, Tpad, mainE, rem, B);
}

// round 6
// speedup vs baseline: 2.1355x; 1.0286x over previous
#include <cuda_runtime.h>
#include <math.h>

#define HOP      160
#define NFFT     512
#define WINLEN   320
#define NMELS    80
#define NBINS    257
#define PREEMPH  0.97f
#define LOG_EPSF 5.9604644775390625e-08f   /* 2^-24 */
#define STD_EPSF 1e-5f
#define BLANKF   27.0f

#define WTAPS    32                 /* padded taps per mel row */
#define FPB      16                 /* frames per block (8 warps x 1 pair) */
#define PB_PITCH 17                 /* pbuf[bin][frame] pitch */
#define PB_BINS  260                /* s4max(228)+32 */
#define YBUF     ((FPB - 1) * HOP + NFFT)   /* 2912 samples staged per block */

/* dynamic smem (floats), zsh overlays ybuf+wwin (disjoint lifetimes):
 * [0,512)          tw    (256 float2)
 * [512,8704)       A:    zsh (8 warps x 1024)  OVERLAYS  ybuf(2912)+wwin(512)
 * [8704,13124)     pbuf  (260*17)
 */
#define SM_TW    0
#define SM_A     512
#define SM_YBUF  SM_A
#define SM_WWIN  (SM_A + YBUF)
#define SM_PBUF  (SM_A + 8 * 1024)
#define SM_FLOATS (SM_PBUF + PB_BINS * PB_PITCH)
#define SMEM_BYTES (SM_FLOATS * 4)          /* 52496 -> 4 CTAs/SM */

__device__ __align__(16) float g_mw[NMELS * WTAPS];
__device__ int    g_mstart[NMELS];
__device__ float2 g_tw[NFFT / 2];
__device__ float  g_win[NFFT];

/* xn may be int32 (JAX default) or int64; lengths >= 160000 so word[1]==0
 * implies int64 layout. Only in-bounds words are read either way. */
__device__ __forceinline__ int load_seqlen(const int* __restrict__ xn32, int b) {
    int is64 = (xn32[1] == 0);
    int v = is64 ? xn32[2 * b] : xn32[b];
    return v / HOP + 1;
}

/* ------------------------------------------------------------------ K0:
 * parallel tables. blocks 0..79: mel row repack; 80: twiddles; 81: window.
 */
__global__ void k_tables(const float* __restrict__ fb) {
    const int m   = blockIdx.x;
    const int tid = threadIdx.x;   /* 64 */

    if (m == NMELS) {
        for (int i = tid; i < NFFT / 2; i += 64) {
            float s, c;
            sincosf((float)i * (-6.283185307179586f / 512.0f), &s, &c);
            g_tw[i] = make_float2(c, s);
        }
        return;
    }
    if (m == NMELS + 1) {
        for (int i = tid; i < NFFT; i += 64) {
            float w = 0.0f;
            if (i >= (NFFT - WINLEN) / 2 && i < (NFFT + WINLEN) / 2) {
                float ph = (float)(i - (NFFT - WINLEN) / 2) *
                           (6.283185307179586f / (float)WINLEN);
                w = 0.5f - 0.5f * cosf(ph);
            }
            g_win[i] = w;
        }
        return;
    }

    __shared__ int sf0, sf1;
    if (tid == 0) { sf0 = NBINS; sf1 = -1; }
    __syncthreads();

    const float* row = fb + m * NBINS;
    int f0 = NBINS, f1 = -1;
    for (int k = tid; k < NBINS; k += 64) {
        if (row[k] != 0.0f) { if (k < f0) f0 = k; if (k > f1) f1 = k; }
    }
    atomicMin(&sf0, f0);
    atomicMax(&sf1, f1);
    __syncthreads();
    f0 = sf0; f1 = sf1;
    if (f1 < 0) { f0 = 0; f1 = 0; }

    int s4 = f0 & ~3;
    if (s4 > NBINS - WTAPS + 3) s4 = (NBINS - WTAPS + 3) & ~3;   /* 228 */
    if (tid == 0) g_mstart[m] = s4;
    for (int j = tid; j < WTAPS; j += 64) {
        int k = s4 + j;
        g_mw[m * WTAPS + j] = (k >= f0 && k <= f1 && k < NBINS) ? row[k] : 0.0f;
    }
}

/* ------------------------------------------------------------------ K1:
 * fused preemph + reflect + window + warp-register pair-FFT + sparse mel.
 * 256 threads, 8 warps, 16 frames per block; one pair-FFT per warp,
 * each thread holds 16 complex points in registers.
 */
__global__ void __launch_bounds__(256)
k_fftmel(const float* __restrict__ x, float* __restrict__ out,
         int L, int T, int Tpad) {
    extern __shared__ float sm[];
    float2* tw  = (float2*)(sm + SM_TW);
    float* ybuf = sm + SM_YBUF;
    float* wwin = sm + SM_WWIN;
    float* pbuf = sm + SM_PBUF;

    const int tid   = threadIdx.x;
    const int w     = tid >> 5;
    const int t     = tid & 31;
    const int b     = blockIdx.y;
    const int tbase = blockIdx.x * FPB;

    /* tables to smem */
    tw[tid] = g_tw[tid];
    wwin[tid]       = g_win[tid];
    wwin[tid + 256] = g_win[tid + 256];

    /* zero mel-tap tail bins (rows 257..259) */
    if (tid < (PB_BINS - NBINS) * PB_PITCH)
        pbuf[NBINS * PB_PITCH + tid] = 0.0f;

    /* stage preemphasized, reflect-padded span */
    const float* xb = x + (size_t)b * L;
    const int jbase = tbase * HOP - NFFT / 2;
    for (int i = tid; i < YBUF; i += 256) {
        int j = jbase + i;
        int jj = (j < 0) ? -j : ((j >= L) ? (2 * L - 2 - j) : j);
        ybuf[i] = (jj == 0) ? xb[0] : (xb[jj] - PREEMPH * xb[jj - 1]);
    }
    __syncthreads();

    const int t0   = tbase + 2 * w;
    const bool has0 = (t0 < T);
    const bool has1 = (t0 + 1 < T);

    float Rr[16], Ri[16];
    const int base = 2 * w * HOP;
    #pragma unroll
    for (int q = 0; q < 16; q++) {
        int i = q * 32 + t;
        float wv = wwin[i];
        Rr[q] = has0 ? ybuf[base + i] * wv : 0.0f;
        Ri[q] = has1 ? ybuf[base + HOP + i] * wv : 0.0f;
    }
    /* all frames now in registers; zsh may overwrite ybuf/wwin */
    __syncthreads();

    /* stages 0..3: within-thread butterflies (partner is another q) */
    #pragma unroll
    for (int s = 0; s < 4; s++) {
        const int qh = 8 >> s;
        #pragma unroll
        for (int qb = 0; qb < 16; qb++) {
            if (!(qb & qh)) {
                const int q1 = qb + qh;
                int idx = (((qb & (qh - 1)) * 32 + t) << s);
                float2 c = tw[idx];
                float ur = Rr[qb], ui = Ri[qb];
                float vr = Rr[q1], vi = Ri[q1];
                float dr = ur - vr, di = ui - vi;
                Rr[qb] = ur + vr;  Ri[qb] = ui + vi;
                Rr[q1] = dr * c.x - di * c.y;
                Ri[q1] = dr * c.y + di * c.x;
            }
        }
    }

    /* stages 4..8: cross-lane via shfl_xor; twiddle depends only on lane */
    #pragma unroll
    for (int s = 4; s < 9; s++) {
        const int hh = 256 >> s;           /* 16,8,4,2,1 */
        float2 c = tw[(t & (hh - 1)) << s];
        const bool up = (t & hh) != 0;
        #pragma unroll
        for (int q = 0; q < 16; q++) {
            float pr = __shfl_xor_sync(0xffffffffu, Rr[q], hh);
            float pi = __shfl_xor_sync(0xffffffffu, Ri[q], hh);
            if (!up) {
                Rr[q] += pr;  Ri[q] += pi;
            } else {
                float dr = pr - Rr[q], di = pi - Ri[q];
                Rr[q] = dr * c.x - di * c.y;
                Ri[q] = dr * c.y + di * c.x;
            }
        }
    }

    /* dump bit-reversed-position data to this warp's smem strip */
    float* zr = sm + SM_A + w * 1024;
    float* zi = zr + 512;
    #pragma unroll
    for (int q = 0; q < 16; q++) {
        zr[q * 32 + t] = Rr[q];
        zi[q * 32 + t] = Ri[q];
    }
    __syncwarp();

    /* unpack packed real pair -> transposed power columns 2w, 2w+1 */
    for (int k = t; k <= NFFT / 2; k += 32) {
        int kn = (NFFT - k) & (NFFT - 1);
        int r1 = __brev(k)  >> 23;
        int r2 = __brev(kn) >> 23;
        float z1r = zr[r1], z1i = zi[r1];
        float z2r = zr[r2], z2i = zi[r2];
        float Ar = 0.5f * (z1r + z2r);
        float Ai = 0.5f * (z1i - z2i);
        float Br = 0.5f * (z1i + z2i);
        float Bi = 0.5f * (z2r - z1r);
        pbuf[k * PB_PITCH + 2 * w]     = Ar * Ar + Ai * Ai;
        pbuf[k * PB_PITCH + 2 * w + 1] = Br * Br + Bi * Bi;
    }
    __syncthreads();

    /* sparse mel + log: 1280 outputs (80 mels x 16 frames) */
    for (int oi = tid; oi < NMELS * FPB; oi += 256) {
        int m    = oi >> 4;
        int tloc = oi & 15;
        int s4   = g_mstart[m];
        const float* wm = g_mw + m * WTAPS;
        const float* pv = pbuf + s4 * PB_PITCH + tloc;
        float acc = 0.0f;
        #pragma unroll
        for (int j = 0; j < WTAPS; j++)
            acc += __ldg(&wm[j]) * pv[j * PB_PITCH];
        int tt = tbase + tloc;
        if (tt < T)
            out[((size_t)b * NMELS + m) * Tpad + tt] = __logf(acc + LOG_EPSF);
    }
}

/* ------------------------------------------------------------------ K2:
 * per-(b,m) single-pass masked mean/var normalization, in-place, BLANK pad.
 * Block (m==0) thread 0 also writes batch b's seq_len tail entry.
 */
__global__ void k_norm(float* __restrict__ out, const int* __restrict__ xn32,
                       int T, int Tpad, size_t mainElems, int rem, int B) {
    __shared__ float rsum[8], rsq[8];

    const int tid  = threadIdx.x;          /* 256 */
    const int lane = tid & 31;
    const int wid  = tid >> 5;
    const int m    = blockIdx.x;
    const int b    = blockIdx.y;

    const int seq = load_seqlen(xn32, b);
    int n = seq;
    if (n < 2) n = 2;
    if (n > T) n = T;

    if (m == 0 && tid == 0 && rem > 0) {
        if (rem == B) {
            out[mainElems + b] = (float)seq;
        } else if (rem == 2 * B) {
            ((long long*)(out + mainElems))[b] = (long long)seq;
        } else if (b == 0) {
            for (int i = 0; i < rem && i < B; i++)
                out[mainElems + i] = (float)load_seqlen(xn32, i);
        }
    }

    float* row = out + ((size_t)b * NMELS + m) * Tpad;

    float lsum = 0.0f, lsq = 0.0f;
    for (int t = tid; t < n; t += 256) {
        float v = row[t];
        lsum += v;
        lsq  += v * v;
    }
    #pragma unroll
    for (int o = 16; o > 0; o >>= 1) {
        lsum += __shfl_xor_sync(0xffffffffu, lsum, o);
        lsq  += __shfl_xor_sync(0xffffffffu, lsq, o);
    }
    if (lane == 0) { rsum[wid] = lsum; rsq[wid] = lsq; }
    __syncthreads();
    float s1 = rsum[lane & 7], s2 = rsq[lane & 7];
    #pragma unroll
    for (int o = 4; o > 0; o >>= 1) {
        s1 += __shfl_xor_sync(0xffffffffu, s1, o);
        s2 += __shfl_xor_sync(0xffffffffu, s2, o);
    }
    /* every warp computed the full total redundantly via its first 8 lanes */
    s1 = __shfl_sync(0xffffffffu, s1, 0);
    s2 = __shfl_sync(0xffffffffu, s2, 0);

    const float fn   = (float)n;
    const float mean = s1 / fn;
    const float var  = (s2 - fn * mean * mean) / (fn - 1.0f);
    const float inv  = 1.0f / (sqrtf(fmaxf(var, 0.0f)) + STD_EPSF);

    for (int t = tid; t < Tpad; t += 256) {
        float o;
        if (t < n)      o = (row[t] - mean) * inv;
        else if (t < T) o = 0.0f;
        else            o = BLANKF;
        row[t] = o;
    }
}

extern "C" void kernel_launch(void* const* d_in, const int* in_sizes, int n_in,
                              void* d_out, int out_size) {
    const float* x    = (const float*)d_in[0];
    const int*   xn32 = (const int*)d_in[1];
    const float* fb   = (const float*)d_in[2];

    const int B    = in_sizes[1];
    const int L    = in_sizes[0] / B;
    const int T    = L / HOP + 1;
    const int Tpad = ((T + 7) / 8) * 8;

    float* out = (float*)d_out;

    cudaFuncSetAttribute(k_fftmel, cudaFuncAttributeMaxDynamicSharedMemorySize,
                         SMEM_BYTES);

    k_tables<<<NMELS + 2, 64>>>(fb);
    k_fftmel<<<dim3((T + FPB - 1) / FPB, B), 256, SMEM_BYTES>>>(x, out, L, T, Tpad);

    size_t mainE = (size_t)B * NMELS * Tpad;
    int rem = out_size - (int)mainE;
    k_norm<<<dim3(NMELS, B), 256>>>(out, xn32, T, Tpad, mainE, rem, B);
}

// round 7
// speedup vs baseline: 2.4518x; 1.1481x over previous
#include <cuda_runtime.h>
#include <math.h>

#define HOP      160
#define NFFT     512
#define WINLEN   320
#define NMELS    80
#define NBINS    257
#define PREEMPH  0.97f
#define LOG_EPSF 5.9604644775390625e-08f   /* 2^-24 */
#define STD_EPSF 1e-5f
#define BLANKF   27.0f

#define WTAPS    32                 /* padded taps per mel row */
#define FPB      16                 /* frames per block (8 warps x 1 pair) */
#define PB_PITCH 268                /* pbuf[frame][bin] pitch: 67x16B, 67%8=3 -> conflict-free LDS.128 */
#define YBUF     ((FPB - 1) * HOP + NFFT)   /* 2912 samples staged per block */

/* dynamic smem (floats), zsh overlays ybuf+wwin (disjoint lifetimes):
 * [0,512)          tw    (256 float2)
 * [512,8704)       A:    zsh (8 warps x 1024)  OVERLAYS  ybuf(2912)+wwin(512)
 * [8704,12992)     pbuf  (16*268) [frame][bin]
 */
#define SM_TW    0
#define SM_A     512
#define SM_YBUF  SM_A
#define SM_WWIN  (SM_A + YBUF)
#define SM_PBUF  (SM_A + 8 * 1024)
#define SM_FLOATS (SM_PBUF + FPB * PB_PITCH)
#define SMEM_BYTES (SM_FLOATS * 4)          /* 51968 B */

__device__ __align__(16) float g_mw[NMELS * WTAPS];
__device__ int    g_mstart[NMELS];
__device__ float2 g_tw[NFFT / 2];
__device__ float  g_win[NFFT];

/* xn may be int32 (JAX default) or int64; lengths >= 160000 so word[1]==0
 * implies int64 layout. Only in-bounds words are read either way. */
__device__ __forceinline__ int load_seqlen(const int* __restrict__ xn32, int b) {
    int is64 = (xn32[1] == 0);
    int v = is64 ? xn32[2 * b] : xn32[b];
    return v / HOP + 1;
}

/* ------------------------------------------------------------------ K0:
 * parallel tables. blocks 0..79: mel row repack; 80: twiddles; 81: window.
 */
__global__ void k_tables(const float* __restrict__ fb) {
    const int m   = blockIdx.x;
    const int tid = threadIdx.x;   /* 64 */

    if (m == NMELS) {
        for (int i = tid; i < NFFT / 2; i += 64) {
            float s, c;
            sincosf((float)i * (-6.283185307179586f / 512.0f), &s, &c);
            g_tw[i] = make_float2(c, s);
        }
        return;
    }
    if (m == NMELS + 1) {
        for (int i = tid; i < NFFT; i += 64) {
            float w = 0.0f;
            if (i >= (NFFT - WINLEN) / 2 && i < (NFFT + WINLEN) / 2) {
                float ph = (float)(i - (NFFT - WINLEN) / 2) *
                           (6.283185307179586f / (float)WINLEN);
                w = 0.5f - 0.5f * cosf(ph);
            }
            g_win[i] = w;
        }
        return;
    }

    __shared__ int sf0, sf1;
    if (tid == 0) { sf0 = NBINS; sf1 = -1; }
    __syncthreads();

    const float* row = fb + m * NBINS;
    int f0 = NBINS, f1 = -1;
    for (int k = tid; k < NBINS; k += 64) {
        if (row[k] != 0.0f) { if (k < f0) f0 = k; if (k > f1) f1 = k; }
    }
    atomicMin(&sf0, f0);
    atomicMax(&sf1, f1);
    __syncthreads();
    f0 = sf0; f1 = sf1;
    if (f1 < 0) { f0 = 0; f1 = 0; }

    int s4 = f0 & ~3;
    if (s4 > NBINS - WTAPS + 3) s4 = (NBINS - WTAPS + 3) & ~3;   /* 228 */
    if (tid == 0) g_mstart[m] = s4;
    for (int j = tid; j < WTAPS; j += 64) {
        int k = s4 + j;
        g_mw[m * WTAPS + j] = (k >= f0 && k <= f1 && k < NBINS) ? row[k] : 0.0f;
    }
}

/* ------------------------------------------------------------------ K1:
 * fused preemph + reflect + window + warp-register pair-FFT + sparse mel.
 * 256 threads, 8 warps, 16 frames per block; one pair-FFT per warp,
 * each thread holds 16 complex points in registers.
 */
__global__ void __launch_bounds__(256, 3)
k_fftmel(const float* __restrict__ x, float* __restrict__ out,
         int L, int T, int Tpad) {
    extern __shared__ float sm[];
    float2* tw  = (float2*)(sm + SM_TW);
    float* ybuf = sm + SM_YBUF;
    float* wwin = sm + SM_WWIN;
    float* pbuf = sm + SM_PBUF;

    const int tid   = threadIdx.x;
    const int w     = tid >> 5;
    const int t     = tid & 31;
    const int b     = blockIdx.y;
    const int tbase = blockIdx.x * FPB;

    /* tables to smem */
    tw[tid] = g_tw[tid];
    wwin[tid]       = g_win[tid];
    wwin[tid + 256] = g_win[tid + 256];

    /* zero mel-tap tail bins (257..259) for all 16 frames */
    if (tid < FPB * 3) {
        int f = tid / 3;
        pbuf[f * PB_PITCH + NBINS + (tid - f * 3)] = 0.0f;
    }

    /* stage preemphasized, reflect-padded span */
    const float* xb = x + (size_t)b * L;
    const int jbase = tbase * HOP - NFFT / 2;
    for (int i = tid; i < YBUF; i += 256) {
        int j = jbase + i;
        int jj = (j < 0) ? -j : ((j >= L) ? (2 * L - 2 - j) : j);
        ybuf[i] = (jj == 0) ? xb[0] : (xb[jj] - PREEMPH * xb[jj - 1]);
    }
    __syncthreads();

    const int t0   = tbase + 2 * w;
    const bool has0 = (t0 < T);
    const bool has1 = (t0 + 1 < T);

    float Rr[16], Ri[16];
    const int base = 2 * w * HOP;
    #pragma unroll
    for (int q = 0; q < 16; q++) {
        int i = q * 32 + t;
        float wv = wwin[i];
        Rr[q] = has0 ? ybuf[base + i] * wv : 0.0f;
        Ri[q] = has1 ? ybuf[base + HOP + i] * wv : 0.0f;
    }
    /* all frames now in registers; zsh may overwrite ybuf/wwin */
    __syncthreads();

    /* stages 0..3: within-thread butterflies (partner is another q) */
    #pragma unroll
    for (int s = 0; s < 4; s++) {
        const int qh = 8 >> s;
        #pragma unroll
        for (int qb = 0; qb < 16; qb++) {
            if (!(qb & qh)) {
                const int q1 = qb + qh;
                int idx = (((qb & (qh - 1)) * 32 + t) << s);
                float2 c = tw[idx];
                float ur = Rr[qb], ui = Ri[qb];
                float vr = Rr[q1], vi = Ri[q1];
                float dr = ur - vr, di = ui - vi;
                Rr[qb] = ur + vr;  Ri[qb] = ui + vi;
                Rr[q1] = dr * c.x - di * c.y;
                Ri[q1] = dr * c.y + di * c.x;
            }
        }
    }

    /* stages 4..8: cross-lane via shfl_xor; twiddle depends only on lane */
    #pragma unroll
    for (int s = 4; s < 9; s++) {
        const int hh = 256 >> s;           /* 16,8,4,2,1 */
        float2 c = tw[(t & (hh - 1)) << s];
        const bool up = (t & hh) != 0;
        #pragma unroll
        for (int q = 0; q < 16; q++) {
            float pr = __shfl_xor_sync(0xffffffffu, Rr[q], hh);
            float pi = __shfl_xor_sync(0xffffffffu, Ri[q], hh);
            if (!up) {
                Rr[q] += pr;  Ri[q] += pi;
            } else {
                float dr = pr - Rr[q], di = pi - Ri[q];
                Rr[q] = dr * c.x - di * c.y;
                Ri[q] = dr * c.y + di * c.x;
            }
        }
    }

    /* dump bit-reversed-position data to this warp's smem strip */
    float* zr = sm + SM_A + w * 1024;
    float* zi = zr + 512;
    #pragma unroll
    for (int q = 0; q < 16; q++) {
        zr[q * 32 + t] = Rr[q];
        zi[q * 32 + t] = Ri[q];
    }
    __syncwarp();

    /* unpack packed real pair -> power rows (frames 2w, 2w+1) */
    for (int k = t; k <= NFFT / 2; k += 32) {
        int kn = (NFFT - k) & (NFFT - 1);
        int r1 = __brev(k)  >> 23;
        int r2 = __brev(kn) >> 23;
        float z1r = zr[r1], z1i = zi[r1];
        float z2r = zr[r2], z2i = zi[r2];
        float Ar = 0.5f * (z1r + z2r);
        float Ai = 0.5f * (z1i - z2i);
        float Br = 0.5f * (z1i + z2i);
        float Bi = 0.5f * (z2r - z1r);
        pbuf[(2 * w) * PB_PITCH + k]     = Ar * Ar + Ai * Ai;
        pbuf[(2 * w + 1) * PB_PITCH + k] = Br * Br + Bi * Bi;
    }
    __syncthreads();

    /* sparse mel + log: 1280 outputs (80 mels x 16 frames), vectorized taps */
    for (int oi = tid; oi < NMELS * FPB; oi += 256) {
        int m    = oi >> 4;
        int tloc = oi & 15;
        int s4   = g_mstart[m];
        const float4* wm = (const float4*)(g_mw + m * WTAPS);
        const float4* pv = (const float4*)(pbuf + tloc * PB_PITCH + s4);
        float acc = 0.0f;
        #pragma unroll
        for (int j = 0; j < WTAPS / 4; j++) {
            float4 f = __ldg(&wm[j]);
            float4 p = pv[j];
            acc += f.x * p.x + f.y * p.y + f.z * p.z + f.w * p.w;
        }
        int tt = tbase + tloc;
        if (tt < T)
            out[((size_t)b * NMELS + m) * Tpad + tt] = __logf(acc + LOG_EPSF);
    }
}

/* ------------------------------------------------------------------ K2:
 * per-(b,m) single-pass masked mean/var normalization, in-place, BLANK pad.
 * Block (m==0) thread 0 also writes batch b's seq_len tail entry.
 */
__global__ void k_norm(float* __restrict__ out, const int* __restrict__ xn32,
                       int T, int Tpad, size_t mainElems, int rem, int B) {
    __shared__ float rsum[8], rsq[8];

    const int tid  = threadIdx.x;          /* 256 */
    const int lane = tid & 31;
    const int wid  = tid >> 5;
    const int m    = blockIdx.x;
    const int b    = blockIdx.y;

    const int seq = load_seqlen(xn32, b);
    int n = seq;
    if (n < 2) n = 2;
    if (n > T) n = T;

    if (m == 0 && tid == 0 && rem > 0) {
        if (rem == B) {
            out[mainElems + b] = (float)seq;
        } else if (rem == 2 * B) {
            ((long long*)(out + mainElems))[b] = (long long)seq;
        } else if (b == 0) {
            for (int i = 0; i < rem && i < B; i++)
                out[mainElems + i] = (float)load_seqlen(xn32, i);
        }
    }

    float* row = out + ((size_t)b * NMELS + m) * Tpad;

    float lsum = 0.0f, lsq = 0.0f;
    for (int t = tid; t < n; t += 256) {
        float v = row[t];
        lsum += v;
        lsq  += v * v;
    }
    #pragma unroll
    for (int o = 16; o > 0; o >>= 1) {
        lsum += __shfl_xor_sync(0xffffffffu, lsum, o);
        lsq  += __shfl_xor_sync(0xffffffffu, lsq, o);
    }
    if (lane == 0) { rsum[wid] = lsum; rsq[wid] = lsq; }
    __syncthreads();
    float s1 = rsum[lane & 7], s2 = rsq[lane & 7];
    #pragma unroll
    for (int o = 4; o > 0; o >>= 1) {
        s1 += __shfl_xor_sync(0xffffffffu, s1, o);
        s2 += __shfl_xor_sync(0xffffffffu, s2, o);
    }
    s1 = __shfl_sync(0xffffffffu, s1, 0);
    s2 = __shfl_sync(0xffffffffu, s2, 0);

    const float fn   = (float)n;
    const float mean = s1 / fn;
    const float var  = (s2 - fn * mean * mean) / (fn - 1.0f);
    const float inv  = 1.0f / (sqrtf(fmaxf(var, 0.0f)) + STD_EPSF);

    for (int t = tid; t < Tpad; t += 256) {
        float o;
        if (t < n)      o = (row[t] - mean) * inv;
        else if (t < T) o = 0.0f;
        else            o = BLANKF;
        row[t] = o;
    }
}

extern "C" void kernel_launch(void* const* d_in, const int* in_sizes, int n_in,
                              void* d_out, int out_size) {
    const float* x    = (const float*)d_in[0];
    const int*   xn32 = (const int*)d_in[1];
    const float* fb   = (const float*)d_in[2];

    const int B    = in_sizes[1];
    const int L    = in_sizes[0] / B;
    const int T    = L / HOP + 1;
    const int Tpad = ((T + 7) / 8) * 8;

    float* out = (float*)d_out;

    cudaFuncSetAttribute(k_fftmel, cudaFuncAttributeMaxDynamicSharedMemorySize,
                         SMEM_BYTES);

    k_tables<<<NMELS + 2, 64>>>(fb);
    k_fftmel<<<dim3((T + FPB - 1) / FPB, B), 256, SMEM_BYTES>>>(x, out, L, T, Tpad);

    size_t mainE = (size_t)B * NMELS * Tpad;
    int rem = out_size - (int)mainE;
    k_norm<<<dim3(NMELS, B), 256>>>(out, xn32, T, Tpad, mainE, rem, B);
}